// round 2
// baseline (speedup 1.0000x reference)
#include <cuda_runtime.h>
#include <cuda_bf16.h>

// Problem constants
#define T_STEPS 512
#define BATCH   256
#define D_IN    512
#define HID     128
#define G4      512   // 4*H
#define YS_ELEMS (T_STEPS * BATCH * HID)   // 16,777,216

typedef unsigned long long ull;

// 256 MB scratch for Xpre = obs @ Wi + b   (T*B x 4H fp32)
__device__ float g_xpre[(size_t)T_STEPS * BATCH * G4];

// ---------- packed fp32x2 helpers (Blackwell) ----------
__device__ __forceinline__ ull fpack2(float lo, float hi) {
    ull r; asm("mov.b64 %0, {%1, %2};" : "=l"(r) : "f"(lo), "f"(hi)); return r;
}
__device__ __forceinline__ ull ffma2(ull a, ull b, ull c) {
    ull d; asm("fma.rn.f32x2 %0, %1, %2, %3;" : "=l"(d) : "l"(a), "l"(b), "l"(c)); return d;
}

// ---------- fast activations (err ~1e-6, safe range here) ----------
__device__ __forceinline__ float sigm_(float x) {
    return __fdividef(1.0f, 1.0f + __expf(-x));
}
__device__ __forceinline__ float tanh_(float x) {
    float e = __expf(-2.0f * x);
    return __fdividef(1.0f - e, 1.0f + e);
}

// ============================================================
// Kernel 1: Xpre[m][n] = bias[n] + sum_k obs[m][k] * Wi[k][n]
//   M = T*B = 131072, N = 512, K = 512
//   BM=128 BN=128 BK=16, 256 threads, 8x8 per thread, f32x2 FMAs
// ============================================================
__global__ __launch_bounds__(256, 2)
void gemm_xpre_kernel(const float* __restrict__ A,   // obs  [M][512]
                      const float* __restrict__ B,   // Wi   [512][512]
                      const float* __restrict__ bias)
{
    __shared__ float As[16][128];   // [k][m]
    __shared__ float Bs[16][128];   // [k][n]

    const int tid = threadIdx.x;
    const int bn  = blockIdx.x;     // 0..3
    const int bm  = blockIdx.y;     // 0..1023

    // global-load assignments
    const int arow  = tid >> 2;            // 0..63
    const int acol4 = (tid & 3) << 2;      // 0,4,8,12
    const int brow  = tid >> 5;            // 0..7
    const int bcol4 = (tid & 31) << 2;     // 0..124

    const float* Ag = A + (size_t)(bm * 128 + arow) * 512 + acol4;
    const float* Bg = B + (size_t)brow * 512 + bn * 128 + bcol4;

    const int tx = tid & 15, ty = tid >> 4;
    const int m0 = ty * 8, n0 = tx * 8;

    ull acc[8][4];
    {
        const float* bp = bias + bn * 128 + n0;
#pragma unroll
        for (int jp = 0; jp < 4; jp++) {
            ull bv = fpack2(bp[2 * jp], bp[2 * jp + 1]);
#pragma unroll
            for (int i = 0; i < 8; i++) acc[i][jp] = bv;
        }
    }

    float4 aR0, aR1, bR0, bR1;
    aR0 = *(const float4*)(Ag);
    aR1 = *(const float4*)(Ag + (size_t)64 * 512);
    bR0 = *(const float4*)(Bg);
    bR1 = *(const float4*)(Bg + (size_t)8 * 512);

    for (int kk = 0; kk < 32; kk++) {
        __syncthreads();
        As[acol4 + 0][arow] = aR0.x;
        As[acol4 + 1][arow] = aR0.y;
        As[acol4 + 2][arow] = aR0.z;
        As[acol4 + 3][arow] = aR0.w;
        As[acol4 + 0][arow + 64] = aR1.x;
        As[acol4 + 1][arow + 64] = aR1.y;
        As[acol4 + 2][arow + 64] = aR1.z;
        As[acol4 + 3][arow + 64] = aR1.w;
        *(float4*)&Bs[brow][bcol4]     = bR0;
        *(float4*)&Bs[brow + 8][bcol4] = bR1;
        __syncthreads();

        if (kk < 31) {
            const float* Ag2 = Ag + (kk + 1) * 16;
            const float* Bg2 = Bg + (size_t)(kk + 1) * 16 * 512;
            aR0 = *(const float4*)(Ag2);
            aR1 = *(const float4*)(Ag2 + (size_t)64 * 512);
            bR0 = *(const float4*)(Bg2);
            bR1 = *(const float4*)(Bg2 + (size_t)8 * 512);
        }

#pragma unroll
        for (int k = 0; k < 16; k++) {
            float4 a0 = *(const float4*)&As[k][m0];
            float4 a1 = *(const float4*)&As[k][m0 + 4];
            ulonglong2 bA = *(const ulonglong2*)&Bs[k][n0];
            ulonglong2 bB = *(const ulonglong2*)&Bs[k][n0 + 4];
            float av[8] = {a0.x, a0.y, a0.z, a0.w, a1.x, a1.y, a1.z, a1.w};
#pragma unroll
            for (int i = 0; i < 8; i++) {
                ull ad = fpack2(av[i], av[i]);
                acc[i][0] = ffma2(ad, bA.x, acc[i][0]);
                acc[i][1] = ffma2(ad, bA.y, acc[i][1]);
                acc[i][2] = ffma2(ad, bB.x, acc[i][2]);
                acc[i][3] = ffma2(ad, bB.y, acc[i][3]);
            }
        }
    }

#pragma unroll
    for (int i = 0; i < 8; i++) {
        float* Cp = g_xpre + (size_t)(bm * 128 + m0 + i) * 512 + bn * 128 + n0;
        *(ull*)&Cp[0] = acc[i][0];
        *(ull*)&Cp[2] = acc[i][1];
        *(ull*)&Cp[4] = acc[i][2];
        *(ull*)&Cp[6] = acc[i][3];
    }
}

// ============================================================
// Kernel 2: persistent time scan. 128 blocks x 256 threads,
// 2 batches per block. Thread t owns gate columns j0=t (weights in
// regs, fp32) and j1=256+t (weights in smem fp32, padded stride 132).
// ============================================================
#define WHS_STRIDE 132
#define SMEM2_FLOATS (256 * WHS_STRIDE + 256 + 1024)
#define SMEM2_BYTES  (SMEM2_FLOATS * 4)

__global__ __launch_bounds__(256, 1)
void lstm_scan_kernel(const float* __restrict__ c0,
                      const float* __restrict__ h0,
                      const int* __restrict__ done,   // bool arrives as int32!
                      const float* __restrict__ Wh,   // [128][512]
                      float* __restrict__ out)
{
    extern __shared__ float smem[];
    float* whs  = smem;                       // [256 cols][132]  (cols 256..511)
    float* hbuf = smem + 256 * WHS_STRIDE;    // [128][2] (b0,b1) interleaved
    float* gbuf = hbuf + 256;                 // [2][512]

    const int tid = threadIdx.x;
    const int blk = blockIdx.x;
    const int b0g = blk * 2, b1g = blk * 2 + 1;

    // --- fill smem weight tile: whs[c][k] = Wh[k][256+c] ---
    for (int i = tid; i < 128 * 256; i += 256) {
        int k = i >> 8, c = i & 255;                  // coalesced over c
        whs[c * WHS_STRIDE + k] = Wh[k * 512 + 256 + c];
    }

    // --- register weights: wreg[k] = Wh[k][tid]  (cols 0..255) ---
    float wreg[128];
#pragma unroll
    for (int k = 0; k < 128; k++) wreg[k] = Wh[k * 512 + tid];

    // --- init h buffer (interleaved by batch) ---
    if (tid < 128) hbuf[tid * 2 + 0] = h0[b0g * 128 + tid];
    else           hbuf[(tid - 128) * 2 + 1] = h0[b1g * 128 + (tid - 128)];

    // --- elementwise identity: thread -> (batch bl, hidden jp) ---
    const int bl = tid >> 7;          // 0/1
    const int jp = tid & 127;
    const int bg = blk * 2 + bl;
    float c_reg = c0[bg * 128 + jp];
    float hlast = 0.0f;

    __syncthreads();

    // --- prefetch t = 0 ---
    float x00, x01, x10, x11;
    int d0v, d1v;
    {
        const float* xp = g_xpre;  // t = 0
        x00 = xp[b0g * 512 + tid];
        x01 = xp[b0g * 512 + 256 + tid];
        x10 = xp[b1g * 512 + tid];
        x11 = xp[b1g * 512 + 256 + tid];
        d0v = done[b0g];
        d1v = done[b1g];
    }

    const float* wrow = whs + tid * WHS_STRIDE;

    for (int t = 0; t < T_STEPS; t++) {
        // prefetch t+1
        float nx00 = 0.f, nx01 = 0.f, nx10 = 0.f, nx11 = 0.f;
        int nd0 = 0, nd1 = 0;
        if (t + 1 < T_STEPS) {
            const float* xp = g_xpre + (size_t)(t + 1) * (BATCH * G4);
            nx00 = xp[b0g * 512 + tid];
            nx01 = xp[b0g * 512 + 256 + tid];
            nx10 = xp[b1g * 512 + tid];
            nx11 = xp[b1g * 512 + 256 + tid];
            nd0 = done[(t + 1) * BATCH + b0g];
            nd1 = done[(t + 1) * BATCH + b1g];
        }

        const float k0 = d0v ? 0.0f : 1.0f;
        const float k1 = d1v ? 0.0f : 1.0f;

        // --- recurrent GEMM: rec = h @ Wh columns (j0, j1), both batches ---
        float rec00 = 0.f, rec01 = 0.f, rec10 = 0.f, rec11 = 0.f;
#pragma unroll
        for (int k = 0; k < 128; k += 4) {
            float4 hA = *(const float4*)&hbuf[2 * k];       // (h0[k],h1[k],h0[k+1],h1[k+1])
            float4 hB = *(const float4*)&hbuf[2 * k + 4];
            float4 w1 = *(const float4*)&wrow[k];
            rec00 = fmaf(hA.x, wreg[k],     rec00);
            rec10 = fmaf(hA.y, wreg[k],     rec10);
            rec01 = fmaf(hA.x, w1.x,        rec01);
            rec11 = fmaf(hA.y, w1.x,        rec11);
            rec00 = fmaf(hA.z, wreg[k + 1], rec00);
            rec10 = fmaf(hA.w, wreg[k + 1], rec10);
            rec01 = fmaf(hA.z, w1.y,        rec01);
            rec11 = fmaf(hA.w, w1.y,        rec11);
            rec00 = fmaf(hB.x, wreg[k + 2], rec00);
            rec10 = fmaf(hB.y, wreg[k + 2], rec10);
            rec01 = fmaf(hB.x, w1.z,        rec01);
            rec11 = fmaf(hB.y, w1.z,        rec11);
            rec00 = fmaf(hB.z, wreg[k + 3], rec00);
            rec10 = fmaf(hB.w, wreg[k + 3], rec10);
            rec01 = fmaf(hB.z, w1.w,        rec01);
            rec11 = fmaf(hB.w, w1.w,        rec11);
        }

        // gates = xpre + keep * rec   (h-reset applied algebraically)
        gbuf[tid]             = fmaf(k0, rec00, x00);
        gbuf[512 + tid]       = fmaf(k1, rec10, x10);
        gbuf[256 + tid]       = fmaf(k0, rec01, x01);
        gbuf[512 + 256 + tid] = fmaf(k1, rec11, x11);
        __syncthreads();

        // --- elementwise LSTM cell ---
        {
            const float* gb = gbuf + bl * 512;
            float gi = gb[jp];
            float gf = gb[128 + jp];
            float gg = gb[256 + jp];
            float go = gb[384 + jp];
            float keep = bl ? k1 : k0;
            float cprev = keep * c_reg;
            float nc = sigm_(gf) * cprev + sigm_(gi) * tanh_(gg);
            float nh = sigm_(go) * tanh_(nc);
            c_reg = nc;
            hlast = nh;
            out[(size_t)(t * BATCH + bg) * 128 + jp] = nh;
            hbuf[jp * 2 + bl] = nh;
        }
        __syncthreads();

        x00 = nx00; x01 = nx01; x10 = nx10; x11 = nx11;
        d0v = nd0;  d1v = nd1;
    }

    // finals: cT then hT after ys
    out[(size_t)YS_ELEMS + bg * 128 + jp] = c_reg;
    out[(size_t)YS_ELEMS + BATCH * HID + bg * 128 + jp] = hlast;
}

// ============================================================
extern "C" void kernel_launch(void* const* d_in, const int* in_sizes, int n_in,
                              void* d_out, int out_size)
{
    const float* c0   = (const float*)d_in[0];
    const float* h0   = (const float*)d_in[1];
    const float* obs  = (const float*)d_in[2];
    const int*   done = (const int*)d_in[3];       // jnp.bool_ -> int32 in harness
    const float* Wi   = (const float*)d_in[4];
    const float* Wh   = (const float*)d_in[5];
    const float* bias = (const float*)d_in[6];
    float* out = (float*)d_out;

    cudaFuncSetAttribute(lstm_scan_kernel,
                         cudaFuncAttributeMaxDynamicSharedMemorySize, SMEM2_BYTES);

    dim3 g1(4, 1024);
    gemm_xpre_kernel<<<g1, 256>>>(obs, Wi, bias);
    lstm_scan_kernel<<<128, 256, SMEM2_BYTES>>>(c0, h0, done, Wh, out);
}

// round 3
// speedup vs baseline: 1.1326x; 1.1326x over previous
#include <cuda_runtime.h>
#include <cuda_bf16.h>

// Problem constants
#define T_STEPS 512
#define BATCH   256
#define D_IN    512
#define HID     128
#define G4      512   // 4*H
#define YS_ELEMS (T_STEPS * BATCH * HID)   // 16,777,216

typedef unsigned long long ull;

// 256 MB scratch for Xpre = obs @ Wi + b   (T*B x 4H fp32)
__device__ float g_xpre[(size_t)T_STEPS * BATCH * G4];

// ---------- packed fp32x2 helpers (Blackwell) ----------
__device__ __forceinline__ ull fpack2(float lo, float hi) {
    ull r; asm("mov.b64 %0, {%1, %2};" : "=l"(r) : "f"(lo), "f"(hi)); return r;
}
__device__ __forceinline__ ull ffma2(ull a, ull b, ull c) {
    ull d; asm("fma.rn.f32x2 %0, %1, %2, %3;" : "=l"(d) : "l"(a), "l"(b), "l"(c)); return d;
}
__device__ __forceinline__ float funpack_add(ull p) {
    float lo, hi; asm("mov.b64 {%0, %1}, %2;" : "=f"(lo), "=f"(hi) : "l"(p));
    return lo + hi;
}

// ---------- fast activations (err ~1e-6, safe range here) ----------
__device__ __forceinline__ float sigm_(float x) {
    return __fdividef(1.0f, 1.0f + __expf(-x));
}
__device__ __forceinline__ float tanh_(float x) {
    float e = __expf(-2.0f * x);
    return __fdividef(1.0f - e, 1.0f + e);
}

// ============================================================
// Kernel 1: Xpre[m][n] = bias[n] + sum_k obs[m][k] * Wi[k][n]
//   M = T*B = 131072, N = 512, K = 512
//   BM=128 BN=128 BK=16, 256 threads, 8x8 per thread, f32x2 FMAs
// ============================================================
__global__ __launch_bounds__(256, 2)
void gemm_xpre_kernel(const float* __restrict__ A,   // obs  [M][512]
                      const float* __restrict__ B,   // Wi   [512][512]
                      const float* __restrict__ bias)
{
    __shared__ float As[16][128];   // [k][m]
    __shared__ float Bs[16][128];   // [k][n]

    const int tid = threadIdx.x;
    const int bn  = blockIdx.x;     // 0..3
    const int bm  = blockIdx.y;     // 0..1023

    // global-load assignments
    const int arow  = tid >> 2;            // 0..63
    const int acol4 = (tid & 3) << 2;      // 0,4,8,12
    const int brow  = tid >> 5;            // 0..7
    const int bcol4 = (tid & 31) << 2;     // 0..124

    const float* Ag = A + (size_t)(bm * 128 + arow) * 512 + acol4;
    const float* Bg = B + (size_t)brow * 512 + bn * 128 + bcol4;

    const int tx = tid & 15, ty = tid >> 4;
    const int m0 = ty * 8, n0 = tx * 8;

    ull acc[8][4];
    {
        const float* bp = bias + bn * 128 + n0;
#pragma unroll
        for (int jp = 0; jp < 4; jp++) {
            ull bv = fpack2(bp[2 * jp], bp[2 * jp + 1]);
#pragma unroll
            for (int i = 0; i < 8; i++) acc[i][jp] = bv;
        }
    }

    float4 aR0, aR1, bR0, bR1;
    aR0 = *(const float4*)(Ag);
    aR1 = *(const float4*)(Ag + (size_t)64 * 512);
    bR0 = *(const float4*)(Bg);
    bR1 = *(const float4*)(Bg + (size_t)8 * 512);

    for (int kk = 0; kk < 32; kk++) {
        __syncthreads();
        As[acol4 + 0][arow] = aR0.x;
        As[acol4 + 1][arow] = aR0.y;
        As[acol4 + 2][arow] = aR0.z;
        As[acol4 + 3][arow] = aR0.w;
        As[acol4 + 0][arow + 64] = aR1.x;
        As[acol4 + 1][arow + 64] = aR1.y;
        As[acol4 + 2][arow + 64] = aR1.z;
        As[acol4 + 3][arow + 64] = aR1.w;
        *(float4*)&Bs[brow][bcol4]     = bR0;
        *(float4*)&Bs[brow + 8][bcol4] = bR1;
        __syncthreads();

        if (kk < 31) {
            const float* Ag2 = Ag + (kk + 1) * 16;
            const float* Bg2 = Bg + (size_t)(kk + 1) * 16 * 512;
            aR0 = *(const float4*)(Ag2);
            aR1 = *(const float4*)(Ag2 + (size_t)64 * 512);
            bR0 = *(const float4*)(Bg2);
            bR1 = *(const float4*)(Bg2 + (size_t)8 * 512);
        }

#pragma unroll
        for (int k = 0; k < 16; k++) {
            float4 a0 = *(const float4*)&As[k][m0];
            float4 a1 = *(const float4*)&As[k][m0 + 4];
            ulonglong2 bA = *(const ulonglong2*)&Bs[k][n0];
            ulonglong2 bB = *(const ulonglong2*)&Bs[k][n0 + 4];
            float av[8] = {a0.x, a0.y, a0.z, a0.w, a1.x, a1.y, a1.z, a1.w};
#pragma unroll
            for (int i = 0; i < 8; i++) {
                ull ad = fpack2(av[i], av[i]);
                acc[i][0] = ffma2(ad, bA.x, acc[i][0]);
                acc[i][1] = ffma2(ad, bA.y, acc[i][1]);
                acc[i][2] = ffma2(ad, bB.x, acc[i][2]);
                acc[i][3] = ffma2(ad, bB.y, acc[i][3]);
            }
        }
    }

#pragma unroll
    for (int i = 0; i < 8; i++) {
        float* Cp = g_xpre + (size_t)(bm * 128 + m0 + i) * 512 + bn * 128 + n0;
        *(ull*)&Cp[0] = acc[i][0];
        *(ull*)&Cp[2] = acc[i][1];
        *(ull*)&Cp[4] = acc[i][2];
        *(ull*)&Cp[6] = acc[i][3];
    }
}

// ============================================================
// Kernel 2: persistent time scan. 128 blocks x 256 threads,
// 2 batches per block. Thread t owns gate columns j0=t (weights in
// 64 packed f32x2 regs) and j1=256+t (weights in smem fp32,
// padded stride 132, read as ulonglong2 pairs).
// Inner loop is pure fma.rn.f32x2 over k-pairs (no pack movs).
// ============================================================
#define WHS_STRIDE 132
// whs: 256*132 | hb0: 132 | hb1: 132 | gbuf: 1024 | pad
#define SMEM2_FLOATS (256 * WHS_STRIDE + 132 + 132 + 1024 + 32)
#define SMEM2_BYTES  (SMEM2_FLOATS * 4)

__global__ __launch_bounds__(256, 1)
void lstm_scan_kernel(const float* __restrict__ c0,
                      const float* __restrict__ h0,
                      const int* __restrict__ done,   // jnp.bool_ arrives as int32
                      const float* __restrict__ Wh,   // [128][512]
                      float* __restrict__ out)
{
    extern __shared__ float smem[];
    float* whs  = smem;                          // [256 cols][132]  (cols 256..511)
    float* hb0  = smem + 256 * WHS_STRIDE;       // h for batch b0, [128]
    float* hb1  = hb0 + 132;                     // h for batch b1, [128]
    float* gbuf = hb1 + 132;                     // [2][512]

    const int tid = threadIdx.x;
    const int blk = blockIdx.x;
    const int b0g = blk * 2, b1g = blk * 2 + 1;

    // --- fill smem weight tile: whs[c][k] = Wh[k][256+c] ---
    for (int i = tid; i < 128 * 256; i += 256) {
        int k = i >> 8, c = i & 255;                  // coalesced over c
        whs[c * WHS_STRIDE + k] = Wh[k * 512 + 256 + c];
    }

    // --- register weights, packed in k-pairs: wreg2[k/2] = (Wh[k][tid], Wh[k+1][tid]) ---
    ull wreg2[64];
#pragma unroll
    for (int k = 0; k < 128; k += 2)
        wreg2[k >> 1] = fpack2(Wh[k * 512 + tid], Wh[(k + 1) * 512 + tid]);

    // --- init h buffers (contiguous per batch) ---
    if (tid < 128) hb0[tid] = h0[b0g * 128 + tid];
    else           hb1[tid - 128] = h0[b1g * 128 + (tid - 128)];

    // --- elementwise identity: thread -> (batch bl, hidden jp) ---
    const int bl = tid >> 7;          // 0/1
    const int jp = tid & 127;
    const int bg = blk * 2 + bl;
    float c_reg = c0[bg * 128 + jp];
    float hlast = 0.0f;

    __syncthreads();

    // --- prefetch t = 0 ---
    float x00, x01, x10, x11;
    int d0v, d1v;
    {
        const float* xp = g_xpre;  // t = 0
        x00 = xp[b0g * 512 + tid];
        x01 = xp[b0g * 512 + 256 + tid];
        x10 = xp[b1g * 512 + tid];
        x11 = xp[b1g * 512 + 256 + tid];
        d0v = done[b0g];
        d1v = done[b1g];
    }

    const float* wrow = whs + tid * WHS_STRIDE;
    float* myh = bl ? hb1 : hb0;

    for (int t = 0; t < T_STEPS; t++) {
        // prefetch t+1
        float nx00 = 0.f, nx01 = 0.f, nx10 = 0.f, nx11 = 0.f;
        int nd0 = 0, nd1 = 0;
        if (t + 1 < T_STEPS) {
            const float* xp = g_xpre + (size_t)(t + 1) * (BATCH * G4);
            nx00 = xp[b0g * 512 + tid];
            nx01 = xp[b0g * 512 + 256 + tid];
            nx10 = xp[b1g * 512 + tid];
            nx11 = xp[b1g * 512 + 256 + tid];
            nd0 = done[(t + 1) * BATCH + b0g];
            nd1 = done[(t + 1) * BATCH + b1g];
        }

        const float k0 = d0v ? 0.0f : 1.0f;
        const float k1 = d1v ? 0.0f : 1.0f;

        // --- recurrent GEMM in packed f32x2 over k-pairs ---
        ull a00 = 0, a01 = 0, a10 = 0, a11 = 0;
#pragma unroll
        for (int k = 0; k < 128; k += 4) {
            ulonglong2 h0v = *(const ulonglong2*)&hb0[k];   // (h[k],h[k+1]) (h[k+2],h[k+3])
            ulonglong2 h1v = *(const ulonglong2*)&hb1[k];
            ulonglong2 w1v = *(const ulonglong2*)&wrow[k];
            ull wA = wreg2[(k >> 1)];
            ull wB = wreg2[(k >> 1) + 1];
            a00 = ffma2(h0v.x, wA,    a00);
            a10 = ffma2(h1v.x, wA,    a10);
            a01 = ffma2(h0v.x, w1v.x, a01);
            a11 = ffma2(h1v.x, w1v.x, a11);
            a00 = ffma2(h0v.y, wB,    a00);
            a10 = ffma2(h1v.y, wB,    a10);
            a01 = ffma2(h0v.y, w1v.y, a01);
            a11 = ffma2(h1v.y, w1v.y, a11);
        }
        float rec00 = funpack_add(a00);
        float rec10 = funpack_add(a10);
        float rec01 = funpack_add(a01);
        float rec11 = funpack_add(a11);

        // gates = xpre + keep * rec   (h-reset applied algebraically)
        gbuf[tid]             = fmaf(k0, rec00, x00);
        gbuf[512 + tid]       = fmaf(k1, rec10, x10);
        gbuf[256 + tid]       = fmaf(k0, rec01, x01);
        gbuf[512 + 256 + tid] = fmaf(k1, rec11, x11);
        __syncthreads();

        // --- elementwise LSTM cell ---
        {
            const float* gb = gbuf + bl * 512;
            float gi = gb[jp];
            float gf = gb[128 + jp];
            float gg = gb[256 + jp];
            float go = gb[384 + jp];
            float keep = bl ? k1 : k0;
            float cprev = keep * c_reg;
            float nc = sigm_(gf) * cprev + sigm_(gi) * tanh_(gg);
            float nh = sigm_(go) * tanh_(nc);
            c_reg = nc;
            hlast = nh;
            out[(size_t)(t * BATCH + bg) * 128 + jp] = nh;
            myh[jp] = nh;
        }
        __syncthreads();

        x00 = nx00; x01 = nx01; x10 = nx10; x11 = nx11;
        d0v = nd0;  d1v = nd1;
    }

    // finals: cT then hT after ys
    out[(size_t)YS_ELEMS + bg * 128 + jp] = c_reg;
    out[(size_t)YS_ELEMS + BATCH * HID + bg * 128 + jp] = hlast;
}

// ============================================================
extern "C" void kernel_launch(void* const* d_in, const int* in_sizes, int n_in,
                              void* d_out, int out_size)
{
    const float* c0   = (const float*)d_in[0];
    const float* h0   = (const float*)d_in[1];
    const float* obs  = (const float*)d_in[2];
    const int*   done = (const int*)d_in[3];       // jnp.bool_ -> int32 in harness
    const float* Wi   = (const float*)d_in[4];
    const float* Wh   = (const float*)d_in[5];
    const float* bias = (const float*)d_in[6];
    float* out = (float*)d_out;

    cudaFuncSetAttribute(lstm_scan_kernel,
                         cudaFuncAttributeMaxDynamicSharedMemorySize, SMEM2_BYTES);

    dim3 g1(4, 1024);
    gemm_xpre_kernel<<<g1, 256>>>(obs, Wi, bias);
    lstm_scan_kernel<<<128, 256, SMEM2_BYTES>>>(c0, h0, done, Wh, out);
}

// round 5
// speedup vs baseline: 1.8656x; 1.6472x over previous
#include <cuda_runtime.h>
#include <cuda_bf16.h>
#include <cstdint>

// Problem constants
#define T_STEPS 512
#define BATCH   256
#define D_IN    512
#define HID     128
#define G4      512   // 4*H
#define YS_ELEMS (T_STEPS * BATCH * HID)
#define M_TOTAL  (T_STEPS * BATCH)        // 131072

typedef unsigned long long ull;

// ---------------- device scratch (static; allowed) ----------------
__device__ float          g_xpre [(size_t)M_TOTAL * G4];       // 256 MB
__device__ __nv_bfloat16  g_obs_hi[(size_t)M_TOTAL * D_IN];    // 128 MB
__device__ __nv_bfloat16  g_obs_lo[(size_t)M_TOTAL * D_IN];    // 128 MB
__device__ __nv_bfloat16  g_wiT_hi[(size_t)G4 * D_IN];         // [n][k]
__device__ __nv_bfloat16  g_wiT_lo[(size_t)G4 * D_IN];

// ---------------- small helpers ----------------
__device__ __forceinline__ ull fpack2(float lo, float hi) {
    ull r; asm("mov.b64 %0, {%1, %2};" : "=l"(r) : "f"(lo), "f"(hi)); return r;
}
__device__ __forceinline__ ull ffma2(ull a, ull b, ull c) {
    ull d; asm("fma.rn.f32x2 %0, %1, %2, %3;" : "=l"(d) : "l"(a), "l"(b), "l"(c)); return d;
}
__device__ __forceinline__ float funpack_add(ull p) {
    float lo, hi; asm("mov.b64 {%0, %1}, %2;" : "=f"(lo), "=f"(hi) : "l"(p));
    return lo + hi;
}
__device__ __forceinline__ float sigm_(float x) {
    return __fdividef(1.0f, 1.0f + __expf(-x));
}
__device__ __forceinline__ float tanh_(float x) {
    float e = __expf(-2.0f * x);
    return __fdividef(1.0f - e, 1.0f + e);
}
__device__ __forceinline__ uint32_t smem_u32(const void* p) {
    uint32_t a;
    asm("{ .reg .u64 t; cvta.to.shared.u64 t, %1; cvt.u32.u64 %0, t; }" : "=r"(a) : "l"(p));
    return a;
}

// SW128 swizzle (byte offsets within a 128B-row tile)
#define SWZ128(o) ((o) ^ (((o) >> 3) & 0x70))

__device__ __forceinline__ void cpasync16(uint32_t s, const void* g) {
    asm volatile("cp.async.cg.shared.global [%0], [%1], 16;" :: "r"(s), "l"(g));
}
__device__ __forceinline__ void ldsm_x4(uint32_t* r, uint32_t addr) {
    asm volatile("ldmatrix.sync.aligned.m8n8.x4.shared.b16 {%0,%1,%2,%3}, [%4];"
        : "=r"(r[0]), "=r"(r[1]), "=r"(r[2]), "=r"(r[3]) : "r"(addr));
}
__device__ __forceinline__ void mma16816(float* c, const uint32_t* a, const uint32_t* b) {
    asm volatile("mma.sync.aligned.m16n8k16.row.col.f32.bf16.bf16.f32 "
        "{%0,%1,%2,%3}, {%4,%5,%6,%7}, {%8,%9}, {%0,%1,%2,%3};"
        : "+f"(c[0]), "+f"(c[1]), "+f"(c[2]), "+f"(c[3])
        : "r"(a[0]), "r"(a[1]), "r"(a[2]), "r"(a[3]), "r"(b[0]), "r"(b[1]));
}

// ============================================================
// Prep 1: split obs fp32 -> bf16 hi/lo
// ============================================================
__global__ __launch_bounds__(256)
void split_obs_kernel(const float* __restrict__ obs) {
    size_t n4 = (size_t)M_TOTAL * D_IN / 4;
    size_t stride = (size_t)gridDim.x * blockDim.x;
    for (size_t i = (size_t)blockIdx.x * blockDim.x + threadIdx.x; i < n4; i += stride) {
        float4 v = ((const float4*)obs)[i];
        __nv_bfloat16 h0 = __float2bfloat16(v.x);
        __nv_bfloat16 h1 = __float2bfloat16(v.y);
        __nv_bfloat16 h2 = __float2bfloat16(v.z);
        __nv_bfloat16 h3 = __float2bfloat16(v.w);
        __nv_bfloat16 l0 = __float2bfloat16(v.x - __bfloat162float(h0));
        __nv_bfloat16 l1 = __float2bfloat16(v.y - __bfloat162float(h1));
        __nv_bfloat16 l2 = __float2bfloat16(v.z - __bfloat162float(h2));
        __nv_bfloat16 l3 = __float2bfloat16(v.w - __bfloat162float(h3));
        ((__nv_bfloat162*)g_obs_hi)[2 * i]     = __nv_bfloat162(h0, h1);
        ((__nv_bfloat162*)g_obs_hi)[2 * i + 1] = __nv_bfloat162(h2, h3);
        ((__nv_bfloat162*)g_obs_lo)[2 * i]     = __nv_bfloat162(l0, l1);
        ((__nv_bfloat162*)g_obs_lo)[2 * i + 1] = __nv_bfloat162(l2, l3);
    }
}

// ============================================================
// Prep 2: transpose + split Wi [k][n] -> WiT hi/lo [n][k]
// ============================================================
__global__ __launch_bounds__(256)
void split_wiT_kernel(const float* __restrict__ Wi) {
    int idx = blockIdx.x * blockDim.x + threadIdx.x;
    if (idx < G4 * D_IN) {
        int n = idx >> 9, k = idx & 511;
        float v = Wi[k * G4 + n];
        __nv_bfloat16 h = __float2bfloat16(v);
        __nv_bfloat16 l = __float2bfloat16(v - __bfloat162float(h));
        g_wiT_hi[idx] = h;
        g_wiT_lo[idx] = l;
    }
}

// ============================================================
// GEMM via mma.sync bf16-split (base-arch HMMA path):
//   Xpre = bias + obs @ Wi  via  Ah*Bh + Ah*Bl + Al*Bh, fp32 acc
//   CTA tile 128m x 128n, K chunks of 64, 2-stage cp.async.
//   8 warps: warp covers 32m x 64n.
// ============================================================
#define GSTAGE 65536          // Ah 16K | Al 16K | Bh 16K | Bl 16K
#define GSM_TOTAL (2 * GSTAGE)

__global__ __launch_bounds__(256, 1)
void gemm_hmma_kernel(const float* __restrict__ bias)
{
    extern __shared__ __align__(1024) char smem[];
    const uint32_t smb = smem_u32(smem);
    const int tid = threadIdx.x;
    const int warp = tid >> 5, lane = tid & 31;
    const int bn = blockIdx.x;     // 0..3
    const int bm = blockIdx.y;     // 0..1023

    const __nv_bfloat16* Agh = g_obs_hi + (size_t)bm * 128 * 512;
    const __nv_bfloat16* Agl = g_obs_lo + (size_t)bm * 128 * 512;
    const __nv_bfloat16* Bgh = g_wiT_hi + (size_t)bn * 128 * 512;
    const __nv_bfloat16* Bgl = g_wiT_lo + (size_t)bn * 128 * 512;

    auto load_stage = [&](int kc, int s) {
        const __nv_bfloat16* srcs[4] = {Agh, Agl, Bgh, Bgl};
        uint32_t sb = smb + s * GSTAGE;
#pragma unroll
        for (int tile = 0; tile < 4; tile++) {
            const __nv_bfloat16* src = srcs[tile];
            uint32_t tb = sb + tile * 16384;
#pragma unroll
            for (int t = 0; t < 4; t++) {
                int i = tid + t * 256;
                int row = i >> 3, cc = i & 7;
                uint32_t so = tb + SWZ128((uint32_t)(row * 128 + cc * 16));
                cpasync16(so, src + (size_t)row * 512 + kc * 64 + cc * 8);
            }
        }
        asm volatile("cp.async.commit_group;" ::: "memory");
    };

    const int wm = (warp & 3) * 32;
    const int wn = (warp >> 2) * 64;
    const int lr = lane & 7, g = lane >> 3;

    float acc[2][8][4];
#pragma unroll
    for (int i = 0; i < 2; i++)
#pragma unroll
        for (int j = 0; j < 8; j++)
#pragma unroll
            for (int q = 0; q < 4; q++) acc[i][j][q] = 0.0f;

    load_stage(0, 0);

    for (int kc = 0; kc < 8; kc++) {
        if (kc + 1 < 8) {
            load_stage(kc + 1, (kc + 1) & 1);
            asm volatile("cp.async.wait_group 1;" ::: "memory");
        } else {
            asm volatile("cp.async.wait_group 0;" ::: "memory");
        }
        __syncthreads();

        uint32_t sb = smb + (kc & 1) * GSTAGE;
#pragma unroll
        for (int ks = 0; ks < 4; ks++) {
            uint32_t ah[2][4], al[2][4];
#pragma unroll
            for (int am = 0; am < 2; am++) {
                int mrow = wm + am * 16 + (g & 1) * 8 + lr;
                int kb = ks * 16 + (g >> 1) * 8;
                uint32_t off = SWZ128((uint32_t)(mrow * 128 + kb * 2));
                ldsm_x4(ah[am], sb + off);
                ldsm_x4(al[am], sb + 16384 + off);
            }
            uint32_t bh[4][4], blf[4][4];
#pragma unroll
            for (int bb = 0; bb < 4; bb++) {
                int nrow = wn + bb * 16 + (g >> 1) * 8 + lr;
                int kb = ks * 16 + (g & 1) * 8;
                uint32_t off = SWZ128((uint32_t)(nrow * 128 + kb * 2));
                ldsm_x4(bh[bb],  sb + 32768 + off);
                ldsm_x4(blf[bb], sb + 49152 + off);
            }
#pragma unroll
            for (int am = 0; am < 2; am++)
#pragma unroll
                for (int bb = 0; bb < 4; bb++)
#pragma unroll
                    for (int h = 0; h < 2; h++) {
                        float* c = acc[am][bb * 2 + h];
                        mma16816(c, ah[am], &bh[bb][h * 2]);
                        mma16816(c, ah[am], &blf[bb][h * 2]);
                        mma16816(c, al[am], &bh[bb][h * 2]);
                    }
        }
        __syncthreads();
    }

    // ---- epilogue: +bias, store fp32 ----
    const int n_base = bn * 128 + wn;
#pragma unroll
    for (int am = 0; am < 2; am++) {
        int row = bm * 128 + wm + am * 16 + (lane >> 2);
#pragma unroll
        for (int b8 = 0; b8 < 8; b8++) {
            int n0 = n_base + b8 * 8 + (lane & 3) * 2;
            float bx = bias[n0], by = bias[n0 + 1];
            float* c = acc[am][b8];
            float2 v0 = make_float2(c[0] + bx, c[1] + by);
            float2 v1 = make_float2(c[2] + bx, c[3] + by);
            *(float2*)(g_xpre + (size_t)row * 512 + n0) = v0;
            *(float2*)(g_xpre + (size_t)(row + 8) * 512 + n0) = v1;
        }
    }
}

// ============================================================
// Kernel 2: persistent time scan (unchanged; measured 723us)
// ============================================================
#define WHS_STRIDE 132
#define SMEM2_FLOATS (256 * WHS_STRIDE + 132 + 132 + 1024 + 32)
#define SMEM2_BYTES  (SMEM2_FLOATS * 4)

__global__ __launch_bounds__(256, 1)
void lstm_scan_kernel(const float* __restrict__ c0,
                      const float* __restrict__ h0,
                      const int* __restrict__ done,   // jnp.bool_ arrives as int32
                      const float* __restrict__ Wh,   // [128][512]
                      float* __restrict__ out)
{
    extern __shared__ float smemf[];
    float* whs  = smemf;
    float* hb0  = smemf + 256 * WHS_STRIDE;
    float* hb1  = hb0 + 132;
    float* gbuf = hb1 + 132;

    const int tid = threadIdx.x;
    const int blk = blockIdx.x;
    const int b0g = blk * 2, b1g = blk * 2 + 1;

    for (int i = tid; i < 128 * 256; i += 256) {
        int k = i >> 8, c = i & 255;
        whs[c * WHS_STRIDE + k] = Wh[k * 512 + 256 + c];
    }

    ull wreg2[64];
#pragma unroll
    for (int k = 0; k < 128; k += 2)
        wreg2[k >> 1] = fpack2(Wh[k * 512 + tid], Wh[(k + 1) * 512 + tid]);

    if (tid < 128) hb0[tid] = h0[b0g * 128 + tid];
    else           hb1[tid - 128] = h0[b1g * 128 + (tid - 128)];

    const int bl = tid >> 7;
    const int jp = tid & 127;
    const int bg = blk * 2 + bl;
    float c_reg = c0[bg * 128 + jp];
    float hlast = 0.0f;

    __syncthreads();

    float x00, x01, x10, x11;
    int d0v, d1v;
    {
        const float* xp = g_xpre;
        x00 = xp[b0g * 512 + tid];
        x01 = xp[b0g * 512 + 256 + tid];
        x10 = xp[b1g * 512 + tid];
        x11 = xp[b1g * 512 + 256 + tid];
        d0v = done[b0g];
        d1v = done[b1g];
    }

    const float* wrow = whs + tid * WHS_STRIDE;
    float* myh = bl ? hb1 : hb0;

    for (int t = 0; t < T_STEPS; t++) {
        float nx00 = 0.f, nx01 = 0.f, nx10 = 0.f, nx11 = 0.f;
        int nd0 = 0, nd1 = 0;
        if (t + 1 < T_STEPS) {
            const float* xp = g_xpre + (size_t)(t + 1) * (BATCH * G4);
            nx00 = xp[b0g * 512 + tid];
            nx01 = xp[b0g * 512 + 256 + tid];
            nx10 = xp[b1g * 512 + tid];
            nx11 = xp[b1g * 512 + 256 + tid];
            nd0 = done[(t + 1) * BATCH + b0g];
            nd1 = done[(t + 1) * BATCH + b1g];
        }

        const float k0 = d0v ? 0.0f : 1.0f;
        const float k1 = d1v ? 0.0f : 1.0f;

        ull a00 = 0, a01 = 0, a10 = 0, a11 = 0;
#pragma unroll
        for (int k = 0; k < 128; k += 4) {
            ulonglong2 h0v = *(const ulonglong2*)&hb0[k];
            ulonglong2 h1v = *(const ulonglong2*)&hb1[k];
            ulonglong2 w1v = *(const ulonglong2*)&wrow[k];
            ull wA = wreg2[(k >> 1)];
            ull wB = wreg2[(k >> 1) + 1];
            a00 = ffma2(h0v.x, wA,    a00);
            a10 = ffma2(h1v.x, wA,    a10);
            a01 = ffma2(h0v.x, w1v.x, a01);
            a11 = ffma2(h1v.x, w1v.x, a11);
            a00 = ffma2(h0v.y, wB,    a00);
            a10 = ffma2(h1v.y, wB,    a10);
            a01 = ffma2(h0v.y, w1v.y, a01);
            a11 = ffma2(h1v.y, w1v.y, a11);
        }
        float rec00 = funpack_add(a00);
        float rec10 = funpack_add(a10);
        float rec01 = funpack_add(a01);
        float rec11 = funpack_add(a11);

        gbuf[tid]             = fmaf(k0, rec00, x00);
        gbuf[512 + tid]       = fmaf(k1, rec10, x10);
        gbuf[256 + tid]       = fmaf(k0, rec01, x01);
        gbuf[512 + 256 + tid] = fmaf(k1, rec11, x11);
        __syncthreads();

        {
            const float* gb = gbuf + bl * 512;
            float gi = gb[jp];
            float gf = gb[128 + jp];
            float gg = gb[256 + jp];
            float go = gb[384 + jp];
            float keep = bl ? k1 : k0;
            float cprev = keep * c_reg;
            float nc = sigm_(gf) * cprev + sigm_(gi) * tanh_(gg);
            float nh = sigm_(go) * tanh_(nc);
            c_reg = nc;
            hlast = nh;
            out[(size_t)(t * BATCH + bg) * 128 + jp] = nh;
            myh[jp] = nh;
        }
        __syncthreads();

        x00 = nx00; x01 = nx01; x10 = nx10; x11 = nx11;
        d0v = nd0;  d1v = nd1;
    }

    out[(size_t)YS_ELEMS + bg * 128 + jp] = c_reg;
    out[(size_t)YS_ELEMS + BATCH * HID + bg * 128 + jp] = hlast;
}

// ============================================================
extern "C" void kernel_launch(void* const* d_in, const int* in_sizes, int n_in,
                              void* d_out, int out_size)
{
    const float* c0   = (const float*)d_in[0];
    const float* h0   = (const float*)d_in[1];
    const float* obs  = (const float*)d_in[2];
    const int*   done = (const int*)d_in[3];       // jnp.bool_ -> int32
    const float* Wi   = (const float*)d_in[4];
    const float* Wh   = (const float*)d_in[5];
    const float* bias = (const float*)d_in[6];
    float* out = (float*)d_out;

    cudaFuncSetAttribute(gemm_hmma_kernel,
                         cudaFuncAttributeMaxDynamicSharedMemorySize, GSM_TOTAL);
    cudaFuncSetAttribute(lstm_scan_kernel,
                         cudaFuncAttributeMaxDynamicSharedMemorySize, SMEM2_BYTES);

    split_obs_kernel<<<1024, 256>>>(obs);
    split_wiT_kernel<<<1024, 256>>>(Wi);
    dim3 gg(4, 1024);
    gemm_hmma_kernel<<<gg, 256, GSM_TOTAL>>>(bias);
    lstm_scan_kernel<<<128, 256, SMEM2_BYTES>>>(c0, h0, done, Wh, out);
}